// round 15
// baseline (speedup 1.0000x reference)
#include <cuda_runtime.h>
#include <cuda_fp16.h>
#include <cstdint>

#define VV 10000
#define BB 4096
#define SS 64
#define EE 128
#define HH 256
#define CC 18
#define NT1 256
#define NT2 512

__device__ __align__(16) float    g_embw[VV * HH];
__device__ __align__(16) uint16_t g_whi16[HH * HH];       // W_hh fp16 swizzled image
__device__ __align__(16) uint16_t g_w1h16[HH * HH];       // W1   fp16 swizzled image
__device__ __align__(16) uint32_t g_lasth32[BB * HH / 2]; // last hidden fp16 pairs

__device__ __forceinline__ float tanh_fast(float x) {
    float y;
    asm("tanh.approx.f32 %0, %1;" : "=f"(y) : "f"(x));
    return y;
}
__device__ __forceinline__ uint32_t smem_u32(const void* p) {
    uint32_t a;
    asm("{ .reg .u64 t; cvta.to.shared.u64 t, %1; cvt.u32.u64 %0, t; }" : "=r"(a) : "l"(p));
    return a;
}
__device__ __forceinline__ void ldm4(uint32_t* d, uint32_t a) {
    asm volatile("ldmatrix.sync.aligned.m8n8.x4.shared.b16 {%0,%1,%2,%3}, [%4];"
                 : "=r"(d[0]), "=r"(d[1]), "=r"(d[2]), "=r"(d[3]) : "r"(a));
}
__device__ __forceinline__ void mma16816(float* c, const uint32_t* a, uint32_t b0, uint32_t b1) {
    asm volatile("mma.sync.aligned.m16n8k16.row.col.f32.f16.f16.f32 "
                 "{%0,%1,%2,%3}, {%4,%5,%6,%7}, {%8,%9}, {%0,%1,%2,%3};"
                 : "+f"(c[0]), "+f"(c[1]), "+f"(c[2]), "+f"(c[3])
                 : "r"(a[0]), "r"(a[1]), "r"(a[2]), "r"(a[3]), "r"(b0), "r"(b1));
}

// ---------------------------------------------------------------------------
// Prep: W_hh and W1 -> fp16 swizzled SMEM images. grid 512.
// ---------------------------------------------------------------------------
__global__ __launch_bounds__(NT1) void prep_w_kernel(
    const float* __restrict__ Whh, const float* __restrict__ W1)
{
    const int i = blockIdx.x * NT1 + threadIdx.x;    // 0..131071
    const float* src = (i < 65536) ? Whh : W1;
    uint16_t* dst = (i < 65536) ? g_whi16 : g_w1h16;
    const int j = i & 65535, n = j >> 8, k = j & 255;
    __half h = __float2half_rn(src[j]);
    dst[n * 256 + (k ^ ((n & 7) << 3))] = *reinterpret_cast<uint16_t*>(&h);
}

// ---------------------------------------------------------------------------
// embW[v][h] = b_ih[h]+b_hh[h]+sum_e emb[v][e]*W_ih[h][e]
// ---------------------------------------------------------------------------
__global__ __launch_bounds__(NT1) void embw_kernel(
    const float* __restrict__ emb, const float* __restrict__ W_ih,
    const float* __restrict__ b_ih, const float* __restrict__ b_hh)
{
    __shared__ float Asm[32][EE];
    __shared__ float Wt[16][HH];
    const int b0 = blockIdx.x * 32;
    const int tid = threadIdx.x;
    {
        const int r = tid >> 3, seg = tid & 7;
        int v = b0 + r; if (v >= VV) v = VV - 1;
        const float4* src = reinterpret_cast<const float4*>(emb + (size_t)v * EE + seg * 16);
        float4* dst = reinterpret_cast<float4*>(&Asm[r][seg * 16]);
#pragma unroll
        for (int q = 0; q < 4; q++) dst[q] = src[q];
    }
    const int r_t = tid >> 5, c_t = tid & 31;
    float acc[4][8];
    {
        float bias[8];
#pragma unroll
        for (int j = 0; j < 8; j++) bias[j] = b_ih[c_t * 8 + j] + b_hh[c_t * 8 + j];
#pragma unroll
        for (int i = 0; i < 4; i++)
#pragma unroll
            for (int j = 0; j < 8; j++) acc[i][j] = bias[j];
    }
    const int kk4 = tid & 3, cbase = tid >> 2;
    for (int k0 = 0; k0 < EE; k0 += 16) {
        __syncthreads();
#pragma unroll
        for (int q = 0; q < 4; q++) {
            const int c = cbase + 64 * q;
            float4 v = *reinterpret_cast<const float4*>(W_ih + (size_t)c * EE + k0 + kk4 * 4);
            Wt[kk4 * 4 + 0][c] = v.x; Wt[kk4 * 4 + 1][c] = v.y;
            Wt[kk4 * 4 + 2][c] = v.z; Wt[kk4 * 4 + 3][c] = v.w;
        }
        __syncthreads();
#pragma unroll
        for (int kk = 0; kk < 16; kk++) {
            float a[4];
#pragma unroll
            for (int i = 0; i < 4; i++) a[i] = Asm[r_t * 4 + i][k0 + kk];
            float w[8];
            *reinterpret_cast<float4*>(w)     = *reinterpret_cast<const float4*>(&Wt[kk][c_t * 8]);
            *reinterpret_cast<float4*>(w + 4) = *reinterpret_cast<const float4*>(&Wt[kk][c_t * 8 + 4]);
#pragma unroll
            for (int i = 0; i < 4; i++)
#pragma unroll
                for (int j = 0; j < 8; j++) acc[i][j] += a[i] * w[j];
        }
    }
#pragma unroll
    for (int i = 0; i < 4; i++) {
        const int v = b0 + r_t * 4 + i;
        if (v < VV) {
            float* dst = g_embw + (size_t)v * HH + c_t * 8;
            *reinterpret_cast<float4*>(dst)     = *reinterpret_cast<float4*>(&acc[i][0]);
            *reinterpret_cast<float4*>(dst + 4) = *reinterpret_cast<float4*>(&acc[i][4]);
        }
    }
}

// ---------------------------------------------------------------------------
// RNN scan: fp16 mma, 512 threads (16 warps, 16 N-cols/warp), Bf in regs.
// dyn smem: Whi 128K | h buffers 2x16K = 160 KB
// ---------------------------------------------------------------------------
__global__ __launch_bounds__(NT2, 1) void rnn_mma_kernel(
    const int* __restrict__ x_in, const int* __restrict__ x_lengths)
{
    extern __shared__ __align__(16) unsigned char dsm[];
    __shared__ int s_xi[SS * 32];
    __shared__ int s_len[32];

    const int tid = threadIdx.x;
    const int w = tid >> 5, l = tid & 31;
    const int b0 = blockIdx.x * 32;
    const uint32_t base = smem_u32(dsm);

    for (int i = tid; i < 8192; i += NT2)
        reinterpret_cast<uint4*>(dsm)[i] = reinterpret_cast<const uint4*>(g_whi16)[i];
    for (int i = tid; i < 4096; i += NT2)
        reinterpret_cast<uint32_t*>(dsm + 131072)[i] = 0;   // zero h buffer 0
    for (int i = tid; i < SS * 32; i += NT2)
        s_xi[(i & 63) * 32 + (i >> 6)] = x_in[b0 * SS + i];
    if (tid < 32) s_len[tid] = x_lengths[b0 + tid];
    __syncthreads();

    const int lq = l & 15, lh = l >> 4;
    const uint32_t sxor = (uint32_t)(l & 7) << 4;

    // hoist this warp's 16-col W slice into registers
    uint32_t Bf[16][4];
#pragma unroll
    for (int k16 = 0; k16 < 16; k16++) {
        const uint32_t koff = (uint32_t)((k16 * 32) | (lh * 16)) ^ sxor;
        ldm4(Bf[k16], base + (w * 16 + lq) * 512 + koff);
    }

    for (int t = 0; t < SS; t++) {
        const uint32_t rb = 131072u + (uint32_t)(t & 1) * 16384u;
        const uint32_t wb = 131072u + (uint32_t)((t + 1) & 1) * 16384u;

        // prefetch epilogue inputs into registers (hidden behind MMA)
        float2 ev[4][2];
        int rr[4]; bool sv[4];
#pragma unroll
        for (int cb = 0; cb < 4; cb++) {
            const int r = (cb >> 1) * 16 + (cb & 1) * 8 + (l >> 2);
            rr[cb] = r;
            const int idx = s_xi[t * 32 + r];
            sv[cb] = (t == s_len[r] - 1);
            const float2* e2 = reinterpret_cast<const float2*>(g_embw + (size_t)idx * HH);
#pragma unroll
            for (int nj = 0; nj < 2; nj++)
                ev[cb][nj] = e2[w * 8 + nj * 4 + (l & 3)];
        }

        float acc[2][2][4];
#pragma unroll
        for (int mi = 0; mi < 2; mi++)
#pragma unroll
            for (int nj = 0; nj < 2; nj++)
#pragma unroll
                for (int c = 0; c < 4; c++) acc[mi][nj][c] = 0.0f;

#pragma unroll
        for (int k16 = 0; k16 < 16; k16++) {
            const uint32_t koff = (uint32_t)((k16 * 32) | (lh * 16)) ^ sxor;
            uint32_t Ah[2][4];
            ldm4(Ah[0], base + rb + lq * 512 + koff);
            ldm4(Ah[1], base + rb + (16 + lq) * 512 + koff);
#pragma unroll
            for (int mi = 0; mi < 2; mi++)
#pragma unroll
                for (int nj = 0; nj < 2; nj++)
                    mma16816(acc[mi][nj], Ah[mi], Bf[k16][nj], Bf[k16][nj + 2]);
        }

        // epilogue: tanh, fp16 round, write to OTHER h buffer
#pragma unroll
        for (int cb = 0; cb < 4; cb++) {
            const int mi = cb >> 1, h8 = cb & 1;
            const int r = rr[cb];
            const uint32_t rxor = (uint32_t)(r & 7) << 4;
#pragma unroll
            for (int nj = 0; nj < 2; nj++) {
                const int ci = w * 8 + nj * 4 + (l & 3);
                float v0 = tanh_fast(acc[mi][nj][h8 * 2]     + ev[cb][nj].x);
                float v1 = tanh_fast(acc[mi][nj][h8 * 2 + 1] + ev[cb][nj].y);
                __half2 hh = __floats2half2_rn(v0, v1);
                *reinterpret_cast<uint32_t*>(dsm + wb + r * 512 + ((uint32_t)(ci * 4) ^ rxor)) =
                    *reinterpret_cast<uint32_t*>(&hh);
                if (sv[cb])
                    g_lasth32[(b0 + r) * 128 + ci] = *reinterpret_cast<uint32_t*>(&hh);
            }
        }
        __syncthreads();
    }
}

// ---------------------------------------------------------------------------
// FC head, 512 threads (16 warps, 16 N-cols/warp), 1-term A; fc2 fused.
// dyn smem: W1 128K | A 16K; y fp32 overlays W1 region after sync.
// ---------------------------------------------------------------------------
__global__ __launch_bounds__(NT2, 1) void fc_mma_kernel(
    const float* __restrict__ b1, const float* __restrict__ W2,
    const float* __restrict__ b2, float* __restrict__ out)
{
    extern __shared__ __align__(16) unsigned char fsm[];
    const int tid = threadIdx.x;
    const int w = tid >> 5, l = tid & 31;
    const int b0 = blockIdx.x * 32;
    const uint32_t base = smem_u32(fsm);

    for (int i = tid; i < 8192; i += NT2)
        reinterpret_cast<uint4*>(fsm)[i] = reinterpret_cast<const uint4*>(g_w1h16)[i];
    for (int i = tid; i < 4096; i += NT2) {
        const int r = i >> 7, j = i & 127;
        const uint32_t off = r * 512 + ((uint32_t)(j * 4) ^ ((uint32_t)(r & 7) << 4));
        *reinterpret_cast<uint32_t*>(fsm + 131072 + off) = g_lasth32[b0 * 128 + i];
    }
    __syncthreads();

    const int lq = l & 15, lh = l >> 4;
    const uint32_t sxor = (uint32_t)(l & 7) << 4;
    float acc[2][2][4];
#pragma unroll
    for (int mi = 0; mi < 2; mi++)
#pragma unroll
        for (int nj = 0; nj < 2; nj++)
#pragma unroll
            for (int c = 0; c < 4; c++) acc[mi][nj][c] = 0.0f;

#pragma unroll
    for (int k16 = 0; k16 < 16; k16++) {
        const uint32_t koff = (uint32_t)((k16 * 32) | (lh * 16)) ^ sxor;
        uint32_t Ah[2][4], Bh[4];
        ldm4(Ah[0], base + 131072 + lq * 512 + koff);
        ldm4(Ah[1], base + 131072 + (16 + lq) * 512 + koff);
        ldm4(Bh, base + (w * 16 + lq) * 512 + koff);
#pragma unroll
        for (int mi = 0; mi < 2; mi++)
#pragma unroll
            for (int nj = 0; nj < 2; nj++)
                mma16816(acc[mi][nj], Ah[mi], Bh[nj], Bh[nj + 2]);
    }
    __syncthreads();   // A/W1 reads done; W1 region becomes y

#pragma unroll
    for (int cb = 0; cb < 4; cb++) {
        const int mi = cb >> 1, h8 = cb & 1;
        const int r = mi * 16 + h8 * 8 + (l >> 2);
#pragma unroll
        for (int nj = 0; nj < 2; nj++) {
            const int c = w * 16 + nj * 8 + (l & 3) * 2;
            float2 bb = *reinterpret_cast<const float2*>(b1 + c);
            float y0 = fmaxf(acc[mi][nj][h8 * 2]     + bb.x, 0.0f);
            float y1 = fmaxf(acc[mi][nj][h8 * 2 + 1] + bb.y, 0.0f);
            *reinterpret_cast<float2*>(fsm + r * 1024 + c * 4) = make_float2(y0, y1);
        }
    }
    __syncthreads();

    for (int e = tid; e < 32 * CC; e += NT2) {
        const int r = e / CC, c = e % CC;
        const float4* yv = reinterpret_cast<const float4*>(fsm + r * 1024);
        const float4* wv = reinterpret_cast<const float4*>(W2 + (size_t)c * HH);
        float s = b2[c];
#pragma unroll 8
        for (int k = 0; k < HH / 4; k++) {
            float4 a = yv[k]; float4 wq = wv[k];
            s += a.x * wq.x + a.y * wq.y + a.z * wq.z + a.w * wq.w;
        }
        out[(size_t)(b0 + r) * CC + c] = s;
    }
}

// ---------------------------------------------------------------------------
extern "C" void kernel_launch(void* const* d_in, const int* in_sizes, int n_in,
                              void* d_out, int out_size)
{
    const int*   x_in  = (const int*)  d_in[0];
    const int*   x_len = (const int*)  d_in[1];
    const float* emb   = (const float*)d_in[2];
    const float* W_ih  = (const float*)d_in[3];
    const float* W_hh  = (const float*)d_in[4];
    const float* b_ih  = (const float*)d_in[5];
    const float* b_hh  = (const float*)d_in[6];
    const float* W1    = (const float*)d_in[7];
    const float* b1    = (const float*)d_in[8];
    const float* W2    = (const float*)d_in[9];
    const float* b2    = (const float*)d_in[10];
    float* out = (float*)d_out;

    const int DSM_RNN = 131072 + 32768;   // Whi + 2x h
    const int DSM_FC  = 131072 + 16384;   // W1 + A-hi (y overlays W1)
    cudaFuncSetAttribute(rnn_mma_kernel, cudaFuncAttributeMaxDynamicSharedMemorySize, DSM_RNN);
    cudaFuncSetAttribute(fc_mma_kernel, cudaFuncAttributeMaxDynamicSharedMemorySize, DSM_FC);

    prep_w_kernel<<<512, NT1>>>(W_hh, W1);
    embw_kernel<<<(VV + 31) / 32, NT1>>>(emb, W_ih, b_ih, b_hh);
    rnn_mma_kernel<<<BB / 32, NT2, DSM_RNN>>>(x_in, x_len);
    fc_mma_kernel<<<BB / 32, NT2, DSM_FC>>>(b1, W2, b2, out);
}

// round 16
// speedup vs baseline: 2.1863x; 2.1863x over previous
#include <cuda_runtime.h>
#include <cuda_fp16.h>
#include <cstdint>

#define VV 10000
#define BB 4096
#define SS 64
#define EE 128
#define HH 256
#define CC 18
#define NTHREADS 256

__device__ __align__(16) float    g_embw[VV * HH];
__device__ __align__(16) uint16_t g_whi16[HH * HH];       // W_hh fp16 swizzled (512B rows)
__device__ __align__(16) uint16_t g_w1h16[HH * HH];       // W1   fp16 swizzled (512B rows)
__device__ __align__(16) uint16_t g_wih16[HH * EE];       // W_ih fp16 swizzled (256B rows)
__device__ __align__(16) uint32_t g_lasth32[BB * HH / 2]; // last hidden fp16 pairs

__device__ __forceinline__ float tanh_fast(float x) {
    float y;
    asm("tanh.approx.f32 %0, %1;" : "=f"(y) : "f"(x));
    return y;
}
__device__ __forceinline__ uint32_t smem_u32(const void* p) {
    uint32_t a;
    asm("{ .reg .u64 t; cvta.to.shared.u64 t, %1; cvt.u32.u64 %0, t; }" : "=r"(a) : "l"(p));
    return a;
}
__device__ __forceinline__ void ldm4(uint32_t* d, uint32_t a) {
    asm volatile("ldmatrix.sync.aligned.m8n8.x4.shared.b16 {%0,%1,%2,%3}, [%4];"
                 : "=r"(d[0]), "=r"(d[1]), "=r"(d[2]), "=r"(d[3]) : "r"(a));
}
__device__ __forceinline__ void mma16816(float* c, const uint32_t* a, uint32_t b0, uint32_t b1) {
    asm volatile("mma.sync.aligned.m16n8k16.row.col.f32.f16.f16.f32 "
                 "{%0,%1,%2,%3}, {%4,%5,%6,%7}, {%8,%9}, {%0,%1,%2,%3};"
                 : "+f"(c[0]), "+f"(c[1]), "+f"(c[2]), "+f"(c[3])
                 : "r"(a[0]), "r"(a[1]), "r"(a[2]), "r"(a[3]), "r"(b0), "r"(b1));
}

// ---------------------------------------------------------------------------
// Prep: W_hh, W1 (256-col rows) and W_ih (128-col rows) -> fp16 swizzled. grid 640.
// ---------------------------------------------------------------------------
__global__ __launch_bounds__(NTHREADS) void prep_w_kernel(
    const float* __restrict__ Whh, const float* __restrict__ W1,
    const float* __restrict__ Wih)
{
    const int i = blockIdx.x * NTHREADS + threadIdx.x;    // 0..163839
    if (i < 131072) {
        const float* src = (i < 65536) ? Whh : W1;
        uint16_t* dst = (i < 65536) ? g_whi16 : g_w1h16;
        const int j = i & 65535, n = j >> 8, k = j & 255;
        __half h = __float2half_rn(src[j]);
        dst[n * 256 + (k ^ ((n & 7) << 3))] = *reinterpret_cast<uint16_t*>(&h);
    } else {
        const int j = i - 131072, n = j >> 7, k = j & 127;
        __half h = __float2half_rn(Wih[j]);
        g_wih16[n * 128 + (k ^ ((n & 7) << 3))] = *reinterpret_cast<uint16_t*>(&h);
    }
}

// ---------------------------------------------------------------------------
// embW via fp16 MMA: E[v][h] = b_ih[h]+b_hh[h] + emb[v]@W_ih^T.
// grid 313, 256 thr. dyn smem: Wih 64K | A 8K = 73728 B.
// ---------------------------------------------------------------------------
__global__ __launch_bounds__(NTHREADS, 3) void embw_mma_kernel(
    const float* __restrict__ emb,
    const float* __restrict__ b_ih, const float* __restrict__ b_hh)
{
    extern __shared__ __align__(16) unsigned char esm[];
    const int tid = threadIdx.x;
    const int w = tid >> 5, l = tid & 31;
    const int b0 = blockIdx.x * 32;
    const uint32_t base = smem_u32(esm);
    const uint32_t Aoff = 65536u;

    for (int i = tid; i < 4096; i += NTHREADS)
        reinterpret_cast<uint4*>(esm)[i] = reinterpret_cast<const uint4*>(g_wih16)[i];
    {   // stage A: 32 emb rows, fp32 -> fp16, swizzled 256B rows
        const int r = tid >> 3, seg = tid & 7;
        int v = b0 + r; if (v >= VV) v = VV - 1;
        const float4* src = reinterpret_cast<const float4*>(emb + (size_t)v * EE + seg * 16);
        float s[16];
#pragma unroll
        for (int q = 0; q < 4; q++) *reinterpret_cast<float4*>(&s[q * 4]) = src[q];
        const uint32_t rx = (uint32_t)(r & 7) << 4;
#pragma unroll
        for (int q = 0; q < 8; q++) {
            __half2 hv = __floats2half2_rn(s[q * 2], s[q * 2 + 1]);
            const uint32_t b = (uint32_t)(seg * 32 + q * 4) ^ rx;
            *reinterpret_cast<uint32_t*>(esm + Aoff + r * 256 + b) =
                *reinterpret_cast<uint32_t*>(&hv);
        }
    }
    __syncthreads();

    const int lq = l & 15, lh = l >> 4;
    const uint32_t sxor = (uint32_t)(l & 7) << 4;
    float acc[2][4][4];
#pragma unroll
    for (int mi = 0; mi < 2; mi++)
#pragma unroll
        for (int nj = 0; nj < 4; nj++)
#pragma unroll
            for (int c = 0; c < 4; c++) acc[mi][nj][c] = 0.0f;

#pragma unroll
    for (int k16 = 0; k16 < 8; k16++) {
        const uint32_t koff = (uint32_t)((k16 * 32) | (lh * 16)) ^ sxor;
        uint32_t Ah[2][4], Bh[2][4];
        ldm4(Ah[0], base + Aoff + lq * 256 + koff);
        ldm4(Ah[1], base + Aoff + (16 + lq) * 256 + koff);
        ldm4(Bh[0], base + (w * 32 + lq) * 256 + koff);
        ldm4(Bh[1], base + (w * 32 + 16 + lq) * 256 + koff);
#pragma unroll
        for (int mi = 0; mi < 2; mi++)
#pragma unroll
            for (int nj = 0; nj < 4; nj++)
                mma16816(acc[mi][nj], Ah[mi],
                         Bh[nj >> 1][nj & 1], Bh[nj >> 1][(nj & 1) + 2]);
    }

#pragma unroll
    for (int cb = 0; cb < 4; cb++) {
        const int mi = cb >> 1, h8 = cb & 1;
        const int r = mi * 16 + h8 * 8 + (l >> 2);
        const int v = b0 + r;
        if (v < VV) {
#pragma unroll
            for (int nj = 0; nj < 4; nj++) {
                const int ci = w * 16 + nj * 4 + (l & 3);
                float2 bi = *reinterpret_cast<const float2*>(b_ih + ci * 2);
                float2 bh = *reinterpret_cast<const float2*>(b_hh + ci * 2);
                float2 o;
                o.x = acc[mi][nj][h8 * 2]     + bi.x + bh.x;
                o.y = acc[mi][nj][h8 * 2 + 1] + bi.y + bh.y;
                *reinterpret_cast<float2*>(g_embw + (size_t)v * HH + ci * 2) = o;
            }
        }
    }
}

// ---------------------------------------------------------------------------
// RNN scan: fp16 mma, 256 thr, Bf hoisted, A ldmatrix pipelined one k16 ahead.
// dyn smem: Whi 128K | h buffers 2x16K = 160 KB
// ---------------------------------------------------------------------------
__global__ __launch_bounds__(NTHREADS, 1) void rnn_mma_kernel(
    const int* __restrict__ x_in, const int* __restrict__ x_lengths)
{
    extern __shared__ __align__(16) unsigned char dsm[];
    __shared__ int s_xi[SS * 32];
    __shared__ int s_len[32];

    const int tid = threadIdx.x;
    const int w = tid >> 5, l = tid & 31;
    const int b0 = blockIdx.x * 32;
    const uint32_t base = smem_u32(dsm);

    for (int i = tid; i < 8192; i += NTHREADS)
        reinterpret_cast<uint4*>(dsm)[i] = reinterpret_cast<const uint4*>(g_whi16)[i];
    for (int i = tid; i < 4096; i += NTHREADS)
        reinterpret_cast<uint32_t*>(dsm + 131072)[i] = 0;
    for (int i = tid; i < SS * 32; i += NTHREADS)
        s_xi[(i & 63) * 32 + (i >> 6)] = x_in[b0 * SS + i];
    if (tid < 32) s_len[tid] = x_lengths[b0 + tid];
    __syncthreads();

    const int lq = l & 15, lh = l >> 4;
    const uint32_t sxor = (uint32_t)(l & 7) << 4;

    uint32_t Bf[16][8];
#pragma unroll
    for (int k16 = 0; k16 < 16; k16++) {
        const uint32_t koff = (uint32_t)((k16 * 32) | (lh * 16)) ^ sxor;
        ldm4(&Bf[k16][0], base + (w * 32 + lq) * 512 + koff);
        ldm4(&Bf[k16][4], base + (w * 32 + 16 + lq) * 512 + koff);
    }

    for (int t = 0; t < SS; t++) {
        const uint32_t rb = 131072u + (uint32_t)(t & 1) * 16384u;
        const uint32_t wb = 131072u + (uint32_t)((t + 1) & 1) * 16384u;

        float2 ev[4][4];
        int rr[4]; bool sv[4];
#pragma unroll
        for (int cb = 0; cb < 4; cb++) {
            const int r = (cb >> 1) * 16 + (cb & 1) * 8 + (l >> 2);
            rr[cb] = r;
            const int idx = s_xi[t * 32 + r];
            sv[cb] = (t == s_len[r] - 1);
            const float2* e2 = reinterpret_cast<const float2*>(g_embw + (size_t)idx * HH);
#pragma unroll
            for (int nj = 0; nj < 4; nj++)
                ev[cb][nj] = e2[w * 16 + nj * 4 + (l & 3)];
        }

        float acc[2][4][4];
#pragma unroll
        for (int mi = 0; mi < 2; mi++)
#pragma unroll
            for (int nj = 0; nj < 4; nj++)
#pragma unroll
                for (int c = 0; c < 4; c++) acc[mi][nj][c] = 0.0f;

        // A ldmatrix pipelined one k16 ahead
        uint32_t Ah[2][2][4];
        {
            const uint32_t koff = (uint32_t)(lh * 16) ^ sxor;
            ldm4(Ah[0][0], base + rb + lq * 512 + koff);
            ldm4(Ah[0][1], base + rb + (16 + lq) * 512 + koff);
        }
#pragma unroll
        for (int k16 = 0; k16 < 16; k16++) {
            const int cur = k16 & 1, nxt = cur ^ 1;
            if (k16 < 15) {
                const uint32_t koff = (uint32_t)(((k16 + 1) * 32) | (lh * 16)) ^ sxor;
                ldm4(Ah[nxt][0], base + rb + lq * 512 + koff);
                ldm4(Ah[nxt][1], base + rb + (16 + lq) * 512 + koff);
            }
#pragma unroll
            for (int mi = 0; mi < 2; mi++)
#pragma unroll
                for (int nj = 0; nj < 4; nj++)
                    mma16816(acc[mi][nj], Ah[cur][mi],
                             Bf[k16][(nj >> 1) * 4 + (nj & 1)],
                             Bf[k16][(nj >> 1) * 4 + (nj & 1) + 2]);
        }

#pragma unroll
        for (int cb = 0; cb < 4; cb++) {
            const int mi = cb >> 1, h8 = cb & 1;
            const int r = rr[cb];
            const uint32_t rxor = (uint32_t)(r & 7) << 4;
#pragma unroll
            for (int nj = 0; nj < 4; nj++) {
                const int ci = w * 16 + nj * 4 + (l & 3);
                float v0 = tanh_fast(acc[mi][nj][h8 * 2]     + ev[cb][nj].x);
                float v1 = tanh_fast(acc[mi][nj][h8 * 2 + 1] + ev[cb][nj].y);
                __half2 hh = __floats2half2_rn(v0, v1);
                *reinterpret_cast<uint32_t*>(dsm + wb + r * 512 + ((uint32_t)(ci * 4) ^ rxor)) =
                    *reinterpret_cast<uint32_t*>(&hh);
                if (sv[cb])
                    g_lasth32[(b0 + r) * 128 + ci] = *reinterpret_cast<uint32_t*>(&hh);
            }
        }
        __syncthreads();
    }
}

// ---------------------------------------------------------------------------
// FC head (R13 shape): 256 thr, grid 128, 1-term A; fc2 fused.
// dyn smem: W1 128K | A 16K; y fp32 overlays W1 region after sync.
// ---------------------------------------------------------------------------
__global__ __launch_bounds__(NTHREADS, 1) void fc_mma_kernel(
    const float* __restrict__ b1, const float* __restrict__ W2,
    const float* __restrict__ b2, float* __restrict__ out)
{
    extern __shared__ __align__(16) unsigned char fsm[];
    const int tid = threadIdx.x;
    const int w = tid >> 5, l = tid & 31;
    const int b0 = blockIdx.x * 32;
    const uint32_t base = smem_u32(fsm);

    for (int i = tid; i < 8192; i += NTHREADS)
        reinterpret_cast<uint4*>(fsm)[i] = reinterpret_cast<const uint4*>(g_w1h16)[i];
    for (int i = tid; i < 4096; i += NTHREADS) {
        const int r = i >> 7, j = i & 127;
        const uint32_t off = r * 512 + ((uint32_t)(j * 4) ^ ((uint32_t)(r & 7) << 4));
        *reinterpret_cast<uint32_t*>(fsm + 131072 + off) = g_lasth32[b0 * 128 + i];
    }
    __syncthreads();

    const int lq = l & 15, lh = l >> 4;
    const uint32_t sxor = (uint32_t)(l & 7) << 4;
    float acc[2][4][4];
#pragma unroll
    for (int mi = 0; mi < 2; mi++)
#pragma unroll
        for (int nj = 0; nj < 4; nj++)
#pragma unroll
            for (int c = 0; c < 4; c++) acc[mi][nj][c] = 0.0f;

#pragma unroll
    for (int k16 = 0; k16 < 16; k16++) {
        const uint32_t koff = (uint32_t)((k16 * 32) | (lh * 16)) ^ sxor;
        uint32_t Ah[2][4], Bh[2][4];
        ldm4(Ah[0], base + 131072 + lq * 512 + koff);
        ldm4(Ah[1], base + 131072 + (16 + lq) * 512 + koff);
        ldm4(Bh[0], base + (w * 32 + lq) * 512 + koff);
        ldm4(Bh[1], base + (w * 32 + 16 + lq) * 512 + koff);
#pragma unroll
        for (int mi = 0; mi < 2; mi++)
#pragma unroll
            for (int nj = 0; nj < 4; nj++)
                mma16816(acc[mi][nj], Ah[mi],
                         Bh[nj >> 1][nj & 1], Bh[nj >> 1][(nj & 1) + 2]);
    }
    __syncthreads();

#pragma unroll
    for (int cb = 0; cb < 4; cb++) {
        const int mi = cb >> 1, h8 = cb & 1;
        const int r = mi * 16 + h8 * 8 + (l >> 2);
#pragma unroll
        for (int nj = 0; nj < 4; nj++) {
            const int c = w * 32 + nj * 8 + (l & 3) * 2;
            float2 bb = *reinterpret_cast<const float2*>(b1 + c);
            float y0 = fmaxf(acc[mi][nj][h8 * 2]     + bb.x, 0.0f);
            float y1 = fmaxf(acc[mi][nj][h8 * 2 + 1] + bb.y, 0.0f);
            *reinterpret_cast<float2*>(fsm + r * 1024 + c * 4) = make_float2(y0, y1);
        }
    }
    __syncthreads();

    for (int e = tid; e < 32 * CC; e += NTHREADS) {
        const int r = e / CC, c = e % CC;
        const float4* yv = reinterpret_cast<const float4*>(fsm + r * 1024);
        const float4* wv = reinterpret_cast<const float4*>(W2 + (size_t)c * HH);
        float s = b2[c];
#pragma unroll 8
        for (int k = 0; k < HH / 4; k++) {
            float4 a = yv[k]; float4 wq = wv[k];
            s += a.x * wq.x + a.y * wq.y + a.z * wq.z + a.w * wq.w;
        }
        out[(size_t)(b0 + r) * CC + c] = s;
    }
}

// ---------------------------------------------------------------------------
extern "C" void kernel_launch(void* const* d_in, const int* in_sizes, int n_in,
                              void* d_out, int out_size)
{
    const int*   x_in  = (const int*)  d_in[0];
    const int*   x_len = (const int*)  d_in[1];
    const float* emb   = (const float*)d_in[2];
    const float* W_ih  = (const float*)d_in[3];
    const float* W_hh  = (const float*)d_in[4];
    const float* b_ih  = (const float*)d_in[5];
    const float* b_hh  = (const float*)d_in[6];
    const float* W1    = (const float*)d_in[7];
    const float* b1    = (const float*)d_in[8];
    const float* W2    = (const float*)d_in[9];
    const float* b2    = (const float*)d_in[10];
    float* out = (float*)d_out;

    const int DSM_RNN  = 131072 + 32768;
    const int DSM_FC   = 131072 + 16384;
    const int DSM_EMBW = 65536 + 8192;
    cudaFuncSetAttribute(rnn_mma_kernel, cudaFuncAttributeMaxDynamicSharedMemorySize, DSM_RNN);
    cudaFuncSetAttribute(fc_mma_kernel, cudaFuncAttributeMaxDynamicSharedMemorySize, DSM_FC);
    cudaFuncSetAttribute(embw_mma_kernel, cudaFuncAttributeMaxDynamicSharedMemorySize, DSM_EMBW);

    prep_w_kernel<<<640, NTHREADS>>>(W_hh, W1, W_ih);
    embw_mma_kernel<<<(VV + 31) / 32, NTHREADS, DSM_EMBW>>>(emb, b_ih, b_hh);
    rnn_mma_kernel<<<BB / 32, NTHREADS, DSM_RNN>>>(x_in, x_len);
    fc_mma_kernel<<<BB / 32, NTHREADS, DSM_FC>>>(b1, W2, b2, out);
}

// round 17
// speedup vs baseline: 2.3114x; 1.0572x over previous
#include <cuda_runtime.h>
#include <cuda_fp16.h>
#include <cstdint>

#define VV 10000
#define BB 4096
#define SS 64
#define EE 128
#define HH 256
#define CC 18
#define NTHREADS 256

__device__ __align__(16) float    g_embw[VV * HH];
__device__ __align__(16) uint16_t g_whi16[HH * HH];       // W_hh fp16 swizzled (512B rows)
__device__ __align__(16) uint16_t g_w1h16[HH * HH];       // W1   fp16 swizzled (512B rows)
__device__ __align__(16) uint16_t g_wih16[HH * EE];       // W_ih fp16 swizzled (256B rows)
__device__ __align__(16) uint32_t g_lasth32[BB * HH / 2]; // last hidden fp16 pairs

__device__ __forceinline__ float tanh_fast(float x) {
    float y;
    asm("tanh.approx.f32 %0, %1;" : "=f"(y) : "f"(x));
    return y;
}
__device__ __forceinline__ uint32_t smem_u32(const void* p) {
    uint32_t a;
    asm("{ .reg .u64 t; cvta.to.shared.u64 t, %1; cvt.u32.u64 %0, t; }" : "=r"(a) : "l"(p));
    return a;
}
__device__ __forceinline__ void cpa16(uint32_t dst, const void* src) {
    asm volatile("cp.async.cg.shared.global [%0], [%1], 16;" :: "r"(dst), "l"(src) : "memory");
}
__device__ __forceinline__ void cpa4(uint32_t dst, const void* src) {
    asm volatile("cp.async.ca.shared.global [%0], [%1], 4;" :: "r"(dst), "l"(src) : "memory");
}
#define CPA_COMMIT() asm volatile("cp.async.commit_group;" ::: "memory")
#define CPA_WAIT()   asm volatile("cp.async.wait_group 0;" ::: "memory")

__device__ __forceinline__ void ldm4(uint32_t* d, uint32_t a) {
    asm volatile("ldmatrix.sync.aligned.m8n8.x4.shared.b16 {%0,%1,%2,%3}, [%4];"
                 : "=r"(d[0]), "=r"(d[1]), "=r"(d[2]), "=r"(d[3]) : "r"(a));
}
__device__ __forceinline__ void mma16816(float* c, const uint32_t* a, uint32_t b0, uint32_t b1) {
    asm volatile("mma.sync.aligned.m16n8k16.row.col.f32.f16.f16.f32 "
                 "{%0,%1,%2,%3}, {%4,%5,%6,%7}, {%8,%9}, {%0,%1,%2,%3};"
                 : "+f"(c[0]), "+f"(c[1]), "+f"(c[2]), "+f"(c[3])
                 : "r"(a[0]), "r"(a[1]), "r"(a[2]), "r"(a[3]), "r"(b0), "r"(b1));
}

// ---------------------------------------------------------------------------
// Prep: W_hh, W1 (256-col rows) and W_ih (128-col rows) -> fp16 swizzled.
// ---------------------------------------------------------------------------
__global__ __launch_bounds__(NTHREADS) void prep_w_kernel(
    const float* __restrict__ Whh, const float* __restrict__ W1,
    const float* __restrict__ Wih)
{
    const int i = blockIdx.x * NTHREADS + threadIdx.x;    // 0..163839
    if (i < 131072) {
        const float* src = (i < 65536) ? Whh : W1;
        uint16_t* dst = (i < 65536) ? g_whi16 : g_w1h16;
        const int j = i & 65535, n = j >> 8, k = j & 255;
        __half h = __float2half_rn(src[j]);
        dst[n * 256 + (k ^ ((n & 7) << 3))] = *reinterpret_cast<uint16_t*>(&h);
    } else {
        const int j = i - 131072, n = j >> 7, k = j & 127;
        __half h = __float2half_rn(Wih[j]);
        g_wih16[n * 128 + (k ^ ((n & 7) << 3))] = *reinterpret_cast<uint16_t*>(&h);
    }
}

// ---------------------------------------------------------------------------
// embW via fp16 MMA: E[v][h] = b_ih[h]+b_hh[h] + emb[v]@W_ih^T.
// grid 313, 256 thr. dyn smem: Wih 64K | A 8K = 73728 B.
// ---------------------------------------------------------------------------
__global__ __launch_bounds__(NTHREADS, 3) void embw_mma_kernel(
    const float* __restrict__ emb,
    const float* __restrict__ b_ih, const float* __restrict__ b_hh)
{
    extern __shared__ __align__(16) unsigned char esm[];
    const int tid = threadIdx.x;
    const int w = tid >> 5, l = tid & 31;
    const int b0 = blockIdx.x * 32;
    const uint32_t base = smem_u32(esm);
    const uint32_t Aoff = 65536u;

#pragma unroll
    for (int q = 0; q < 16; q++)
        cpa16(base + (tid + q * NTHREADS) * 16,
              reinterpret_cast<const uint4*>(g_wih16) + tid + q * NTHREADS);
    CPA_COMMIT();
    {   // stage A: 32 emb rows, fp32 -> fp16, swizzled 256B rows
        const int r = tid >> 3, seg = tid & 7;
        int v = b0 + r; if (v >= VV) v = VV - 1;
        const float4* src = reinterpret_cast<const float4*>(emb + (size_t)v * EE + seg * 16);
        float s[16];
#pragma unroll
        for (int q = 0; q < 4; q++) *reinterpret_cast<float4*>(&s[q * 4]) = src[q];
        const uint32_t rx = (uint32_t)(r & 7) << 4;
#pragma unroll
        for (int q = 0; q < 8; q++) {
            __half2 hv = __floats2half2_rn(s[q * 2], s[q * 2 + 1]);
            const uint32_t b = (uint32_t)(seg * 32 + q * 4) ^ rx;
            *reinterpret_cast<uint32_t*>(esm + Aoff + r * 256 + b) =
                *reinterpret_cast<uint32_t*>(&hv);
        }
    }
    CPA_WAIT();
    __syncthreads();

    const int lq = l & 15, lh = l >> 4;
    const uint32_t sxor = (uint32_t)(l & 7) << 4;
    float acc[2][4][4];
#pragma unroll
    for (int mi = 0; mi < 2; mi++)
#pragma unroll
        for (int nj = 0; nj < 4; nj++)
#pragma unroll
            for (int c = 0; c < 4; c++) acc[mi][nj][c] = 0.0f;

#pragma unroll
    for (int k16 = 0; k16 < 8; k16++) {
        const uint32_t koff = (uint32_t)((k16 * 32) | (lh * 16)) ^ sxor;
        uint32_t Ah[2][4], Bh[2][4];
        ldm4(Ah[0], base + Aoff + lq * 256 + koff);
        ldm4(Ah[1], base + Aoff + (16 + lq) * 256 + koff);
        ldm4(Bh[0], base + (w * 32 + lq) * 256 + koff);
        ldm4(Bh[1], base + (w * 32 + 16 + lq) * 256 + koff);
#pragma unroll
        for (int mi = 0; mi < 2; mi++)
#pragma unroll
            for (int nj = 0; nj < 4; nj++)
                mma16816(acc[mi][nj], Ah[mi],
                         Bh[nj >> 1][nj & 1], Bh[nj >> 1][(nj & 1) + 2]);
    }

#pragma unroll
    for (int cb = 0; cb < 4; cb++) {
        const int mi = cb >> 1, h8 = cb & 1;
        const int r = mi * 16 + h8 * 8 + (l >> 2);
        const int v = b0 + r;
        if (v < VV) {
#pragma unroll
            for (int nj = 0; nj < 4; nj++) {
                const int ci = w * 16 + nj * 4 + (l & 3);
                float2 bi = *reinterpret_cast<const float2*>(b_ih + ci * 2);
                float2 bh = *reinterpret_cast<const float2*>(b_hh + ci * 2);
                float2 o;
                o.x = acc[mi][nj][h8 * 2]     + bi.x + bh.x;
                o.y = acc[mi][nj][h8 * 2 + 1] + bi.y + bh.y;
                *reinterpret_cast<float2*>(g_embw + (size_t)v * HH + ci * 2) = o;
            }
        }
    }
}

// ---------------------------------------------------------------------------
// RNN scan: fp16 mma, 256 thr, Bf hoisted, A ldmatrix pipelined, cp.async stage.
// dyn smem: Whi 128K | h buffers 2x16K = 160 KB
// ---------------------------------------------------------------------------
__global__ __launch_bounds__(NTHREADS, 1) void rnn_mma_kernel(
    const int* __restrict__ x_in, const int* __restrict__ x_lengths)
{
    extern __shared__ __align__(16) unsigned char dsm[];
    __shared__ int s_xi[SS * 32];
    __shared__ int s_len[32];

    const int tid = threadIdx.x;
    const int w = tid >> 5, l = tid & 31;
    const int b0 = blockIdx.x * 32;
    const uint32_t base = smem_u32(dsm);

#pragma unroll
    for (int q = 0; q < 32; q++)
        cpa16(base + (tid + q * NTHREADS) * 16,
              reinterpret_cast<const uint4*>(g_whi16) + tid + q * NTHREADS);
    CPA_COMMIT();
    for (int i = tid; i < 4096; i += NTHREADS)
        reinterpret_cast<uint32_t*>(dsm + 131072)[i] = 0;
    for (int i = tid; i < SS * 32; i += NTHREADS)
        s_xi[(i & 63) * 32 + (i >> 6)] = x_in[b0 * SS + i];
    if (tid < 32) s_len[tid] = x_lengths[b0 + tid];
    CPA_WAIT();
    __syncthreads();

    const int lq = l & 15, lh = l >> 4;
    const uint32_t sxor = (uint32_t)(l & 7) << 4;

    uint32_t Bf[16][8];
#pragma unroll
    for (int k16 = 0; k16 < 16; k16++) {
        const uint32_t koff = (uint32_t)((k16 * 32) | (lh * 16)) ^ sxor;
        ldm4(&Bf[k16][0], base + (w * 32 + lq) * 512 + koff);
        ldm4(&Bf[k16][4], base + (w * 32 + 16 + lq) * 512 + koff);
    }

    for (int t = 0; t < SS; t++) {
        const uint32_t rb = 131072u + (uint32_t)(t & 1) * 16384u;
        const uint32_t wb = 131072u + (uint32_t)((t + 1) & 1) * 16384u;

        float2 ev[4][4];
        int rr[4]; bool sv[4];
#pragma unroll
        for (int cb = 0; cb < 4; cb++) {
            const int r = (cb >> 1) * 16 + (cb & 1) * 8 + (l >> 2);
            rr[cb] = r;
            const int idx = s_xi[t * 32 + r];
            sv[cb] = (t == s_len[r] - 1);
            const float2* e2 = reinterpret_cast<const float2*>(g_embw + (size_t)idx * HH);
#pragma unroll
            for (int nj = 0; nj < 4; nj++)
                ev[cb][nj] = e2[w * 16 + nj * 4 + (l & 3)];
        }

        float acc[2][4][4];
#pragma unroll
        for (int mi = 0; mi < 2; mi++)
#pragma unroll
            for (int nj = 0; nj < 4; nj++)
#pragma unroll
                for (int c = 0; c < 4; c++) acc[mi][nj][c] = 0.0f;

        uint32_t Ah[2][2][4];
        {
            const uint32_t koff = (uint32_t)(lh * 16) ^ sxor;
            ldm4(Ah[0][0], base + rb + lq * 512 + koff);
            ldm4(Ah[0][1], base + rb + (16 + lq) * 512 + koff);
        }
#pragma unroll
        for (int k16 = 0; k16 < 16; k16++) {
            const int cur = k16 & 1, nxt = cur ^ 1;
            if (k16 < 15) {
                const uint32_t koff = (uint32_t)(((k16 + 1) * 32) | (lh * 16)) ^ sxor;
                ldm4(Ah[nxt][0], base + rb + lq * 512 + koff);
                ldm4(Ah[nxt][1], base + rb + (16 + lq) * 512 + koff);
            }
#pragma unroll
            for (int mi = 0; mi < 2; mi++)
#pragma unroll
                for (int nj = 0; nj < 4; nj++)
                    mma16816(acc[mi][nj], Ah[cur][mi],
                             Bf[k16][(nj >> 1) * 4 + (nj & 1)],
                             Bf[k16][(nj >> 1) * 4 + (nj & 1) + 2]);
        }

#pragma unroll
        for (int cb = 0; cb < 4; cb++) {
            const int mi = cb >> 1, h8 = cb & 1;
            const int r = rr[cb];
            const uint32_t rxor = (uint32_t)(r & 7) << 4;
#pragma unroll
            for (int nj = 0; nj < 4; nj++) {
                const int ci = w * 16 + nj * 4 + (l & 3);
                float v0 = tanh_fast(acc[mi][nj][h8 * 2]     + ev[cb][nj].x);
                float v1 = tanh_fast(acc[mi][nj][h8 * 2 + 1] + ev[cb][nj].y);
                __half2 hh = __floats2half2_rn(v0, v1);
                *reinterpret_cast<uint32_t*>(dsm + wb + r * 512 + ((uint32_t)(ci * 4) ^ rxor)) =
                    *reinterpret_cast<uint32_t*>(&hh);
                if (sv[cb])
                    g_lasth32[(b0 + r) * 128 + ci] = *reinterpret_cast<uint32_t*>(&hh);
            }
        }
        __syncthreads();
    }
}

// ---------------------------------------------------------------------------
// FC head: 256 thr, grid 128, 1-term A, cp.async staging; fc2 fused.
// dyn smem: W1 128K | A 16K; y fp32 overlays W1 region after sync.
// ---------------------------------------------------------------------------
__global__ __launch_bounds__(NTHREADS, 1) void fc_mma_kernel(
    const float* __restrict__ b1, const float* __restrict__ W2,
    const float* __restrict__ b2, float* __restrict__ out)
{
    extern __shared__ __align__(16) unsigned char fsm[];
    const int tid = threadIdx.x;
    const int w = tid >> 5, l = tid & 31;
    const int b0 = blockIdx.x * 32;
    const uint32_t base = smem_u32(fsm);

#pragma unroll
    for (int q = 0; q < 32; q++)
        cpa16(base + (tid + q * NTHREADS) * 16,
              reinterpret_cast<const uint4*>(g_w1h16) + tid + q * NTHREADS);
#pragma unroll
    for (int q = 0; q < 16; q++) {
        const int i = tid + q * NTHREADS;
        const int r = i >> 7, j = i & 127;
        const uint32_t off = r * 512 + ((uint32_t)(j * 4) ^ ((uint32_t)(r & 7) << 4));
        cpa4(base + 131072 + off, g_lasth32 + b0 * 128 + i);
    }
    CPA_COMMIT();
    CPA_WAIT();
    __syncthreads();

    const int lq = l & 15, lh = l >> 4;
    const uint32_t sxor = (uint32_t)(l & 7) << 4;
    float acc[2][4][4];
#pragma unroll
    for (int mi = 0; mi < 2; mi++)
#pragma unroll
        for (int nj = 0; nj < 4; nj++)
#pragma unroll
            for (int c = 0; c < 4; c++) acc[mi][nj][c] = 0.0f;

#pragma unroll
    for (int k16 = 0; k16 < 16; k16++) {
        const uint32_t koff = (uint32_t)((k16 * 32) | (lh * 16)) ^ sxor;
        uint32_t Ah[2][4], Bh[2][4];
        ldm4(Ah[0], base + 131072 + lq * 512 + koff);
        ldm4(Ah[1], base + 131072 + (16 + lq) * 512 + koff);
        ldm4(Bh[0], base + (w * 32 + lq) * 512 + koff);
        ldm4(Bh[1], base + (w * 32 + 16 + lq) * 512 + koff);
#pragma unroll
        for (int mi = 0; mi < 2; mi++)
#pragma unroll
            for (int nj = 0; nj < 4; nj++)
                mma16816(acc[mi][nj], Ah[mi],
                         Bh[nj >> 1][nj & 1], Bh[nj >> 1][(nj & 1) + 2]);
    }
    __syncthreads();   // A/W1 reads done; W1 region becomes y

#pragma unroll
    for (int cb = 0; cb < 4; cb++) {
        const int mi = cb >> 1, h8 = cb & 1;
        const int r = mi * 16 + h8 * 8 + (l >> 2);
#pragma unroll
        for (int nj = 0; nj < 4; nj++) {
            const int c = w * 32 + nj * 8 + (l & 3) * 2;
            float2 bb = *reinterpret_cast<const float2*>(b1 + c);
            float y0 = fmaxf(acc[mi][nj][h8 * 2]     + bb.x, 0.0f);
            float y1 = fmaxf(acc[mi][nj][h8 * 2 + 1] + bb.y, 0.0f);
            *reinterpret_cast<float2*>(fsm + r * 1024 + c * 4) = make_float2(y0, y1);
        }
    }
    __syncthreads();

    for (int e = tid; e < 32 * CC; e += NTHREADS) {
        const int r = e / CC, c = e % CC;
        const float4* yv = reinterpret_cast<const float4*>(fsm + r * 1024);
        const float4* wv = reinterpret_cast<const float4*>(W2 + (size_t)c * HH);
        float s = b2[c];
#pragma unroll 8
        for (int k = 0; k < HH / 4; k++) {
            float4 a = yv[k]; float4 wq = wv[k];
            s += a.x * wq.x + a.y * wq.y + a.z * wq.z + a.w * wq.w;
        }
        out[(size_t)(b0 + r) * CC + c] = s;
    }
}

// ---------------------------------------------------------------------------
extern "C" void kernel_launch(void* const* d_in, const int* in_sizes, int n_in,
                              void* d_out, int out_size)
{
    const int*   x_in  = (const int*)  d_in[0];
    const int*   x_len = (const int*)  d_in[1];
    const float* emb   = (const float*)d_in[2];
    const float* W_ih  = (const float*)d_in[3];
    const float* W_hh  = (const float*)d_in[4];
    const float* b_ih  = (const float*)d_in[5];
    const float* b_hh  = (const float*)d_in[6];
    const float* W1    = (const float*)d_in[7];
    const float* b1    = (const float*)d_in[8];
    const float* W2    = (const float*)d_in[9];
    const float* b2    = (const float*)d_in[10];
    float* out = (float*)d_out;

    const int DSM_RNN  = 131072 + 32768;
    const int DSM_FC   = 131072 + 16384;
    const int DSM_EMBW = 65536 + 8192;
    cudaFuncSetAttribute(rnn_mma_kernel, cudaFuncAttributeMaxDynamicSharedMemorySize, DSM_RNN);
    cudaFuncSetAttribute(fc_mma_kernel, cudaFuncAttributeMaxDynamicSharedMemorySize, DSM_FC);
    cudaFuncSetAttribute(embw_mma_kernel, cudaFuncAttributeMaxDynamicSharedMemorySize, DSM_EMBW);

    prep_w_kernel<<<640, NTHREADS>>>(W_hh, W1, W_ih);
    embw_mma_kernel<<<(VV + 31) / 32, NTHREADS, DSM_EMBW>>>(emb, b_ih, b_hh);
    rnn_mma_kernel<<<BB / 32, NTHREADS, DSM_RNN>>>(x_in, x_len);
    fc_mma_kernel<<<BB / 32, NTHREADS, DSM_FC>>>(b1, W2, b2, out);
}